// round 8
// baseline (speedup 1.0000x reference)
#include <cuda_runtime.h>

// GCN: h1 = relu(GCNConv(x, W1, b1)); h2 = GCNConv(h1, W2, b2);
// g = segment_sum(h2, batch); out = log_softmax(g @ Wlin + blin)
//
// out[c] = dinv[c] * ( sum_{e: col=c} hs[row] + hs[c] ) + b,  hs = (x@W)*dinv.
// CSR built on device with per-node segments PADDED to multiples of 8 using a
// dummy node (index NN, features fixed at zero) -> tail-free, divergence-free
// gather with aligned int4 index loads. Scratch buffers self-reset for graph
// replay (no init kernel).

static const int NN = 100000;
static const int NG = 1024;
static const int EMAX = 3200000;
static const int SMAX = EMAX + 7 * NN + 8;  // padded slot capacity

// Scratch (device globals; zero-initialized at module load; no allocation)
__device__ int    g_is64;
__device__ int    g_batch32[NN];
__device__ int    g_degi[NN];          // re-zeroed by k_scan after use
__device__ int    g_start[NN + 1];
__device__ int    g_cursor[NN];
__device__ int    g_srcs[SMAX];
__device__ __align__(16) float g_dinv[NN];
__device__ float4 g_hs1[(NN + 1) * 4]; // slot NN = dummy, stays zero forever
__device__ float4 g_hs2[(NN + 1) * 4]; // slot NN = dummy, stays zero forever
__device__ float4 g_pool[NG * 4];      // re-zeroed by k_logits after use

__device__ __forceinline__ void red_add_v4(float* addr, float4 v) {
    asm volatile("red.global.add.v4.f32 [%0], {%1, %2, %3, %4};"
                 :: "l"(addr), "f"(v.x), "f"(v.y), "f"(v.z), "f"(v.w)
                 : "memory");
}

__device__ __forceinline__ void acc4(float4& a, const float4 b) {
    a.x += b.x; a.y += b.y; a.z += b.z; a.w += b.w;
}

// ---------------------------------------------------------------------------
// 1) dtype detect (1 block): int64 indices < 2^31 have all-zero high words.
__global__ void k_detect(const void* __restrict__ ei, int twoE) {
    __shared__ int bad;
    if (threadIdx.x == 0) bad = 0;
    __syncthreads();
    const long long* p64 = (const long long*)ei;
    int n = twoE / 2 < 2048 ? twoE / 2 : 2048;
    for (int k = threadIdx.x; k < n; k += blockDim.x) {
        unsigned long long v = (unsigned long long)p64[k];
        if (v >> 32) bad = 1;   // benign race
    }
    __syncthreads();
    if (threadIdx.x == 0) g_is64 = bad ? 0 : 1;
}

// 2) degree count over raw cols + fused batch conversion (g_degi starts 0)
__global__ void k_deg(const void* __restrict__ ei, const void* __restrict__ batch,
                      int E) {
    int i = blockIdx.x * blockDim.x + threadIdx.x;
    int is64 = g_is64;
    if (i < E) {
        int c = is64 ? (int)((const long long*)ei)[E + i]
                     : ((const int*)ei)[E + i];
        atomicAdd(&g_degi[c], 1);
    }
    if (i < NN) {
        g_batch32[i] = is64 ? (int)((const long long*)batch)[i]
                            : ((const int*)batch)[i];
    }
}

// 3) single-block scan: padded-degree prefix sum -> starts/cursors/dinv.
//    Also re-zeroes g_degi for the next graph replay.
__global__ void k_scan() {
    const int CH = (NN + 1023) / 1024;   // 98
    __shared__ int sh[1024];
    int t  = threadIdx.x;
    int lo = t * CH;
    int hi = lo + CH < NN ? lo + CH : NN;
    int sum = 0;
    for (int i = lo; i < hi; i++)
        sum += (g_degi[i] + 7) & ~7;     // padded degree
    sh[t] = sum;
    __syncthreads();
    for (int off = 1; off < 1024; off <<= 1) {
        int a = (t >= off) ? sh[t - off] : 0;
        __syncthreads();
        sh[t] += a;
        __syncthreads();
    }
    int run = sh[t] - sum;               // exclusive offset for this chunk
    for (int i = lo; i < hi; i++) {
        int d = g_degi[i];
        g_degi[i]   = 0;                 // reset for next replay
        g_start[i]  = run;
        g_cursor[i] = run;
        g_dinv[i]   = rsqrtf((float)(d + 1));   // +1 self loop
        run += (d + 7) & ~7;
    }
    if (t == 0) g_start[NN] = sh[1023];
}

// 4) bucket edge sources by target (raw reads, cursor-ordered writes)
__global__ void k_bucket(const void* __restrict__ ei, int E) {
    int e = blockIdx.x * blockDim.x + threadIdx.x;
    if (e >= E) return;
    int r, c;
    if (g_is64) {
        r = (int)((const long long*)ei)[e];
        c = (int)((const long long*)ei)[E + e];
    } else {
        r = ((const int*)ei)[e];
        c = ((const int*)ei)[E + e];
    }
    int pos = atomicAdd(&g_cursor[c], 1);
    g_srcs[pos] = r;
}

// 5) hs1 = (x @ W1) * dinv  + fill this node's pad slots with dummy index NN
__global__ void k_hs1(const float* __restrict__ x, const float* __restrict__ W1) {
    __shared__ float sW[48];
    if (threadIdx.x < 48) sW[threadIdx.x] = W1[threadIdx.x];
    __syncthreads();
    int i = blockIdx.x * blockDim.x + threadIdx.x;
    if (i >= NN) return;
    // pad fill: cursor is now start+deg (bucket completed before this launch)
    int pend = g_start[i + 1];
    for (int p = g_cursor[i]; p < pend; p++) g_srcs[p] = NN;
    float x0 = __ldg(x + 3 * i + 0);
    float x1 = __ldg(x + 3 * i + 1);
    float x2 = __ldg(x + 3 * i + 2);
    float di = g_dinv[i];
    float h[16];
#pragma unroll
    for (int j = 0; j < 16; j++)
        h[j] = di * (x0 * sW[j] + x1 * sW[16 + j] + x2 * sW[32 + j]);
    float4* dst = &g_hs1[i * 4];
    dst[0] = make_float4(h[0],  h[1],  h[2],  h[3]);
    dst[1] = make_float4(h[4],  h[5],  h[6],  h[7]);
    dst[2] = make_float4(h[8],  h[9],  h[10], h[11]);
    dst[3] = make_float4(h[12], h[13], h[14], h[15]);
}

// gather body: segments are multiples of 8 -> tail-free, aligned int4 indices
__device__ __forceinline__ float4 gather_q(const float4* __restrict__ hs,
                                           int node, int q) {
    float4 acc = __ldg(hs + node * 4 + q);
    int e  = g_start[node];
    int e2 = g_start[node + 1];
    for (; e < e2; e += 8) {
        int4 ra = __ldg((const int4*)(g_srcs + e));
        int4 rb = __ldg((const int4*)(g_srcs + e + 4));
        float4 v0 = __ldg(hs + ra.x * 4 + q);
        float4 v1 = __ldg(hs + ra.y * 4 + q);
        float4 v2 = __ldg(hs + ra.z * 4 + q);
        float4 v3 = __ldg(hs + ra.w * 4 + q);
        float4 v4 = __ldg(hs + rb.x * 4 + q);
        float4 v5 = __ldg(hs + rb.y * 4 + q);
        float4 v6 = __ldg(hs + rb.z * 4 + q);
        float4 v7 = __ldg(hs + rb.w * 4 + q);
        acc4(acc, v0); acc4(acc, v1); acc4(acc, v2); acc4(acc, v3);
        acc4(acc, v4); acc4(acc, v5); acc4(acc, v6); acc4(acc, v7);
    }
    return acc;
}

// 6) layer1: gather + relu + 16x16 matmul via warp shuffles (4 lanes/node)
__global__ void k_layer1(const float* __restrict__ b1, const float* __restrict__ W2) {
    __shared__ float sW[256];
    __shared__ float sb[16];
    if (threadIdx.x < 256) sW[threadIdx.x] = W2[threadIdx.x];
    if (threadIdx.x < 16)  sb[threadIdx.x] = b1[threadIdx.x];
    __syncthreads();
    int t = blockIdx.x * blockDim.x + threadIdx.x;
    int node = t >> 2;
    int q = t & 3;
    if (node >= NN) return;
    float4 acc = gather_q(g_hs1, node, q);
    float di = g_dinv[node];
    float4 myv;
    myv.x = fmaxf(fmaf(di, acc.x, sb[q * 4 + 0]), 0.f);
    myv.y = fmaxf(fmaf(di, acc.y, sb[q * 4 + 1]), 0.f);
    myv.z = fmaxf(fmaf(di, acc.z, sb[q * 4 + 2]), 0.f);
    myv.w = fmaxf(fmaf(di, acc.w, sb[q * 4 + 3]), 0.f);
    int lane = threadIdx.x & 31;
    int base = lane & ~3;
    float o0 = 0.f, o1 = 0.f, o2 = 0.f, o3 = 0.f;
#pragma unroll
    for (int p = 0; p < 4; p++) {
        float4 vp;
        vp.x = __shfl_sync(0xffffffff, myv.x, base + p);
        vp.y = __shfl_sync(0xffffffff, myv.y, base + p);
        vp.z = __shfl_sync(0xffffffff, myv.z, base + p);
        vp.w = __shfl_sync(0xffffffff, myv.w, base + p);
        const float* w0 = &sW[(p * 4 + 0) * 16 + q * 4];
        const float* w1 = &sW[(p * 4 + 1) * 16 + q * 4];
        const float* w2 = &sW[(p * 4 + 2) * 16 + q * 4];
        const float* w3 = &sW[(p * 4 + 3) * 16 + q * 4];
        o0 = fmaf(vp.x, w0[0], fmaf(vp.y, w1[0], fmaf(vp.z, w2[0], fmaf(vp.w, w3[0], o0))));
        o1 = fmaf(vp.x, w0[1], fmaf(vp.y, w1[1], fmaf(vp.z, w2[1], fmaf(vp.w, w3[1], o1))));
        o2 = fmaf(vp.x, w0[2], fmaf(vp.y, w1[2], fmaf(vp.z, w2[2], fmaf(vp.w, w3[2], o2))));
        o3 = fmaf(vp.x, w0[3], fmaf(vp.y, w1[3], fmaf(vp.z, w2[3], fmaf(vp.w, w3[3], o3))));
    }
    g_hs2[node * 4 + q] = make_float4(di * o0, di * o1, di * o2, di * o3);
}

// 7) layer2: gather + bias + pool reduction
__global__ void k_layer2(const float* __restrict__ b2) {
    __shared__ float sb[16];
    if (threadIdx.x < 16) sb[threadIdx.x] = b2[threadIdx.x];
    __syncthreads();
    int t = blockIdx.x * blockDim.x + threadIdx.x;
    int node = t >> 2;
    int q = t & 3;
    if (node >= NN) return;
    float4 acc = gather_q(g_hs2, node, q);
    float di = g_dinv[node];
    int g = g_batch32[node];
    float4 r;
    r.x = fmaf(di, acc.x, sb[q * 4 + 0]);
    r.y = fmaf(di, acc.y, sb[q * 4 + 1]);
    r.z = fmaf(di, acc.z, sb[q * 4 + 2]);
    r.w = fmaf(di, acc.w, sb[q * 4 + 3]);
    red_add_v4((float*)&g_pool[g * 4 + q], r);
}

// 8) per-graph head: logits = pool @ Wlin + blin; log_softmax.
//    Re-zeroes g_pool for the next graph replay.
__global__ void k_logits(const float* __restrict__ Wlin, const float* __restrict__ blin,
                         float* __restrict__ out) {
    int g = blockIdx.x * blockDim.x + threadIdx.x;
    if (g >= NG) return;
    float gv[16];
    float4 z = make_float4(0.f, 0.f, 0.f, 0.f);
#pragma unroll
    for (int q = 0; q < 4; q++) {
        float4 p = g_pool[g * 4 + q];
        g_pool[g * 4 + q] = z;           // reset for next replay
        gv[q * 4 + 0] = p.x; gv[q * 4 + 1] = p.y;
        gv[q * 4 + 2] = p.z; gv[q * 4 + 3] = p.w;
    }
    float lg[7];
#pragma unroll
    for (int o = 0; o < 7; o++) {
        float acc = __ldg(blin + o);
#pragma unroll
        for (int k = 0; k < 16; k++)
            acc = fmaf(gv[k], __ldg(Wlin + k * 7 + o), acc);
        lg[o] = acc;
    }
    float m = lg[0];
#pragma unroll
    for (int o = 1; o < 7; o++) m = fmaxf(m, lg[o]);
    float s = 0.f;
#pragma unroll
    for (int o = 0; o < 7; o++) s += expf(lg[o] - m);
    float ls = logf(s) + m;
#pragma unroll
    for (int o = 0; o < 7; o++) out[g * 7 + o] = lg[o] - ls;
}

// ---------------------------------------------------------------------------
extern "C" void kernel_launch(void* const* d_in, const int* in_sizes, int n_in,
                              void* d_out, int out_size) {
    int p = 0;
    const float* x     = (const float*)d_in[p]; p++;
    const void*  ei    = d_in[p];
    int twoE = in_sizes[p];
    int E = twoE / 2; p++;
    const void*  batch = d_in[p]; p++;
    if (p < n_in && in_sizes[p] == 1) p++;  // skip scalar num_graphs if present
    const float* W1   = (const float*)d_in[p]; p++;
    const float* b1   = (const float*)d_in[p]; p++;
    const float* W2   = (const float*)d_in[p]; p++;
    const float* b2   = (const float*)d_in[p]; p++;
    const float* Wlin = (const float*)d_in[p]; p++;
    const float* blin = (const float*)d_in[p]; p++;
    float* out = (float*)d_out;

    const int TB = 256;
    int gN  = (NN + TB - 1) / TB;
    int gN4 = (NN * 4 + TB - 1) / TB;
    int gE  = (E + TB - 1) / TB;

    k_detect <<<1,    TB>>>(ei, twoE);
    k_deg    <<<gE,   TB>>>(ei, batch, E);
    k_scan   <<<1,    1024>>>();
    k_bucket <<<gE,   TB>>>(ei, E);
    k_hs1    <<<gN,   TB>>>(x, W1);
    k_layer1 <<<gN4,  TB>>>(b1, W2);
    k_layer2 <<<gN4,  TB>>>(b2);
    k_logits <<<(NG + TB - 1) / TB, TB>>>(Wlin, blin, out);
}